// round 13
// baseline (speedup 1.0000x reference)
#include <cuda_runtime.h>
#include <math.h>
#include <stdint.h>

// Problem dims (fixed by the dataset)
#define TT 8192
#define DD 1024
#define HH 4096
#define EE 8

// GEMM tiling
#define BM 128
#define BN 128
#define BK 16
#define TM 8
#define TN 8
#define AROWF 264  // A smem row stride in floats: 128 duplicated pairs (256) + 8 pad
#define ROWF 144   // B smem row stride in floats (576B); 16 8-float tiles w/ 4-float pad per 4

// ---------------- scratch (static device globals; no allocations) ----------
__device__ int   g_count[EE];
__device__ int   g_cursor[EE];
__device__ int   g_offset[EE];
__device__ int   g_sel[TT * 2];
__device__ float g_wt[TT * 2];
__device__ int   g_btok[TT * 2];
__device__ float g_bw[TT * 2];
__device__ int   g_pos[TT * 2];
__device__ float g_h[(size_t)TT * 2 * HH];
__device__ float g_yb[(size_t)TT * 2 * DD];

// ---------------- f32x2 helpers ----------------------------------------------
__device__ __forceinline__ void fma2(unsigned long long& d, unsigned long long a,
                                     unsigned long long b) {
    asm("fma.rn.f32x2 %0, %1, %2, %0;" : "+l"(d) : "l"(a), "l"(b));
}
__device__ __forceinline__ float2 unpack2(unsigned long long v) {
    float2 r;
    asm("mov.b64 {%0, %1}, %2;" : "=f"(r.x), "=f"(r.y) : "l"(v));
    return r;
}

// Fast exact-enough GELU: erf via Abramowitz-Stegun 7.1.26 (|err| <= 1.5e-7).
__device__ __forceinline__ float fast_gelu(float z) {
    float x = fabsf(z) * 0.70710678118654752f;
    float t = __fdividef(1.f, fmaf(0.3275911f, x, 1.f));
    float p = t * fmaf(t, fmaf(t, fmaf(t, fmaf(t, 1.061405429f, -1.453152027f),
                                       1.421413741f), -0.284496736f), 0.254829592f);
    float er = fmaf(-p, __expf(-x * x), 1.f);   // erf(|x|)
    er = copysignf(er, z);
    return 0.5f * z * (1.f + er);
}

// B smem float-offset for an 8-float tile p (0..15): p*8 + (p>>2)*4.
// No overlaps; bank-verified conflict-free for LDS.128 loads and STS stores.
__device__ __forceinline__ int bskew(int p) { return p * 8 + (p >> 2) * 4; }

// ---------------- kernels ---------------------------------------------------

__global__ void k_zero() {
    if (threadIdx.x < EE) g_count[threadIdx.x] = 0;
}

__global__ void k_router(const float* __restrict__ x, const float* __restrict__ Wg,
                         float* __restrict__ out_logits) {
    int t = blockIdx.x * (blockDim.x >> 5) + (threadIdx.x >> 5);
    int lane = threadIdx.x & 31;
    if (t >= TT) return;
    const float* xr = x + (size_t)t * DD;

    float acc[EE];
#pragma unroll
    for (int e = 0; e < EE; e++) acc[e] = 0.f;
    for (int j = lane; j < DD; j += 32) {
        float xv = xr[j];
#pragma unroll
        for (int e = 0; e < EE; e++) acc[e] = fmaf(xv, Wg[e * DD + j], acc[e]);
    }
#pragma unroll
    for (int e = 0; e < EE; e++) {
#pragma unroll
        for (int o = 16; o > 0; o >>= 1) acc[e] += __shfl_xor_sync(0xffffffffu, acc[e], o);
    }
    if (lane == 0) {
        float mx = acc[0];
#pragma unroll
        for (int e = 1; e < EE; e++) mx = fmaxf(mx, acc[e]);
        float p[EE];
        float den = 0.f;
#pragma unroll
        for (int e = 0; e < EE; e++) { p[e] = expf(acc[e] - mx); den += p[e]; }
        float inv = 1.f / den;
#pragma unroll
        for (int e = 0; e < EE; e++) p[e] *= inv;

        int i0 = 0;
#pragma unroll
        for (int e = 1; e < EE; e++) if (p[e] > p[i0]) i0 = e;
        int i1 = (i0 == 0) ? 1 : 0;
#pragma unroll
        for (int e = 0; e < EE; e++) if (e != i0 && p[e] > p[i1]) i1 = e;

        float w0 = p[i0], w1 = p[i1];
        float s = 1.f / (w0 + w1);
        w0 *= s; w1 *= s;

        g_sel[t * 2] = i0; g_sel[t * 2 + 1] = i1;
        g_wt[t * 2] = w0;  g_wt[t * 2 + 1] = w1;
        atomicAdd(&g_count[i0], 1);
        atomicAdd(&g_count[i1], 1);
#pragma unroll
        for (int e = 0; e < EE; e++) out_logits[(size_t)t * EE + e] = acc[e];
    }
}

__global__ void k_offsets() {
    int o = 0;
    for (int e = 0; e < EE; e++) { g_offset[e] = o; g_cursor[e] = o; o += g_count[e]; }
}

__global__ void k_scatter() {
    int t = blockIdx.x * blockDim.x + threadIdx.x;
    if (t >= TT) return;
#pragma unroll
    for (int k = 0; k < 2; k++) {
        int e = g_sel[t * 2 + k];
        int idx = atomicAdd(&g_cursor[e], 1);
        g_btok[idx] = t;
        g_bw[idx] = g_wt[t * 2 + k];
        g_pos[t * 2 + k] = idx;
    }
}

// Grouped GEMM (fp32, packed f32x2 FMA, conflict-free smem, pre-splatted A).
// UP=true:  g_h[idx]  = gelu(x[gather] @ W1[e]) * gate
// UP=false: g_yb[idx] = g_h[idx] @ W2[e]
template<int KD, int ND, bool UP>
__global__ __launch_bounds__(256, 2)
void k_ggemm(const float* __restrict__ Ag, const float* __restrict__ Bg) {
    const int e = blockIdx.z;
    const int cnt = g_count[e];
    const int rt = blockIdx.y;
    if (rt * BM >= cnt) return;
    const int off = g_offset[e];
    const int n0 = blockIdx.x * BN;
    const int tid = threadIdx.x;

    __shared__ __align__(16) float As[2][BK][AROWF];  // duplicated pairs: col 2r,2r+1 = A[r]
    __shared__ __align__(16) float Bs[2][BK][ROWF];
    __shared__ int stok[BM];

    if (UP) {
        if (tid < BM) {
            int gr = rt * BM + tid;
            stok[tid] = g_btok[off + ((gr < cnt) ? gr : (cnt - 1))];
        }
    }
    __syncthreads();

    const float* Bexp = Bg + (size_t)e * KD * ND;

    // global-load slots
    const int ar0 = tid >> 2, ak4 = tid & 3;
    const int ar1 = ar0 + 64;
    const float* a_src0;
    const float* a_src1;
    if (UP) {
        a_src0 = Ag + (size_t)stok[ar0] * KD + ak4 * 4;
        a_src1 = Ag + (size_t)stok[ar1] * KD + ak4 * 4;
    } else {
        int g0 = rt * BM + ar0; if (g0 >= cnt) g0 = cnt - 1;
        int g1 = rt * BM + ar1; if (g1 >= cnt) g1 = cnt - 1;
        a_src0 = g_h + (size_t)(off + g0) * KD + ak4 * 4;
        a_src1 = g_h + (size_t)(off + g1) * KD + ak4 * 4;
    }
    const int bkk0 = tid >> 5, bn4 = tid & 31;
    const float* b_src0 = Bexp + (size_t)bkk0 * ND + n0 + bn4 * 4;
    const float* b_src1 = b_src0 + (size_t)8 * ND;
    // skewed store offset for this thread's float4 within a Bs row
    const int bso = bskew(bn4 >> 1) + (bn4 & 1) * 4;

    float4 pa0, pa1, pb0, pb1;

    auto fetch = [&](int kt) {
        pa0 = *(const float4*)(a_src0 + kt);
        pa1 = *(const float4*)(a_src1 + kt);
        pb0 = *(const float4*)(b_src0 + (size_t)kt * ND);
        pb1 = *(const float4*)(b_src1 + (size_t)kt * ND);
    };
    auto store = [&](int buf) {
#pragma unroll
        for (int c = 0; c < 4; c++) {
            float v0 = (&pa0.x)[c];
            float v1 = (&pa1.x)[c];
            *(float2*)&As[buf][ak4 * 4 + c][2 * ar0] = make_float2(v0, v0);
            *(float2*)&As[buf][ak4 * 4 + c][2 * ar1] = make_float2(v1, v1);
        }
        *(float4*)&Bs[buf][bkk0][bso]     = pb0;
        *(float4*)&Bs[buf][bkk0 + 8][bso] = pb1;
    };

    unsigned long long acc2[TM][TN / 2];
#pragma unroll
    for (int i = 0; i < TM; i++)
#pragma unroll
        for (int j = 0; j < TN / 2; j++) acc2[i][j] = 0ull;

    fetch(0);
    store(0);
    __syncthreads();

    // lane mapping: warp 4(M)x2(N); lane 4(M)x8(N)
    const int lane = tid & 31, wid = tid >> 5;
    const int wm = wid & 3, wn = wid >> 2;
    const int my = lane >> 3, nx = lane & 7;
    const int arow = wm * 32 + my * 8;          // thread's first M row in tile
    const int bofs = bskew(wn * 8 + nx);        // thread's skewed B float offset

    const int NK = KD / BK;
    for (int kt = 0; kt < NK; kt++) {
        const int cur = kt & 1;
        if (kt + 1 < NK) fetch((kt + 1) * BK);
#pragma unroll
        for (int k = 0; k < BK; k++) {
            // pre-splatted A pairs: each ulonglong2 = {a_i,a_i, a_{i+1},a_{i+1}}
            ulonglong2 a01 = *(const ulonglong2*)&As[cur][k][2 * arow];
            ulonglong2 a23 = *(const ulonglong2*)&As[cur][k][2 * arow + 4];
            ulonglong2 a45 = *(const ulonglong2*)&As[cur][k][2 * arow + 8];
            ulonglong2 a67 = *(const ulonglong2*)&As[cur][k][2 * arow + 12];
            ulonglong2 b01 = *(const ulonglong2*)&Bs[cur][k][bofs];
            ulonglong2 b23 = *(const ulonglong2*)&Bs[cur][k][bofs + 4];
            unsigned long long bp0 = b01.x, bp1 = b01.y, bp2 = b23.x, bp3 = b23.y;
            unsigned long long ap[TM] = {a01.x, a01.y, a23.x, a23.y,
                                         a45.x, a45.y, a67.x, a67.y};
#pragma unroll
            for (int i = 0; i < TM; i++) {
                fma2(acc2[i][0], ap[i], bp0);
                fma2(acc2[i][1], ap[i], bp1);
                fma2(acc2[i][2], ap[i], bp2);
                fma2(acc2[i][3], ap[i], bp3);
            }
        }
        if (kt + 1 < NK) store(cur ^ 1);
        __syncthreads();
    }

    // epilogue: thread owns rows arow..arow+7, cols wn*64+nx*8..+8
    const int cc = wn * 64 + nx * 8;
#pragma unroll
    for (int i = 0; i < TM; i++) {
        int gr = rt * BM + arow + i;
        if (gr >= cnt) continue;
        float* crow;
        float gate = 1.f;
        if (UP) {
            gate = g_bw[off + gr];
            crow = g_h + (size_t)(off + gr) * ND;
        } else {
            crow = g_yb + (size_t)(off + gr) * ND;
        }
#pragma unroll
        for (int j2 = 0; j2 < TN / 2; j2 += 2) {
            float2 v0 = unpack2(acc2[i][j2]);
            float2 v1 = unpack2(acc2[i][j2 + 1]);
            float vv[4] = {v0.x, v0.y, v1.x, v1.y};
            if (UP) {
#pragma unroll
                for (int q = 0; q < 4; q++) {
                    vv[q] = fast_gelu(vv[q]) * gate;
                }
            }
            *(float4*)(crow + n0 + cc + j2 * 2) = make_float4(vv[0], vv[1], vv[2], vv[3]);
        }
    }
}

__global__ void k_combine(float* __restrict__ y) {
    int i = blockIdx.x * blockDim.x + threadIdx.x;
    const int nv = TT * DD / 4;
    if (i >= nv) return;
    int t = i / (DD / 4);
    int d4 = i % (DD / 4);
    int p0 = g_pos[2 * t], p1 = g_pos[2 * t + 1];
    float4 a = ((const float4*)(g_yb + (size_t)p0 * DD))[d4];
    float4 b = ((const float4*)(g_yb + (size_t)p1 * DD))[d4];
    float4 o = make_float4(a.x + b.x, a.y + b.y, a.z + b.z, a.w + b.w);
    ((float4*)(y + (size_t)t * DD))[d4] = o;
}

// ---------------- launch -----------------------------------------------------

extern "C" void kernel_launch(void* const* d_in, const int* in_sizes, int n_in,
                              void* d_out, int out_size) {
    const float* x  = (const float*)d_in[0];
    const float* Wg = (const float*)d_in[1];
    const float* W1 = (const float*)d_in[2];
    const float* W2 = (const float*)d_in[3];
    float* out = (float*)d_out;
    float* y = out;                                 // [T, D]
    float* logits = out + (size_t)TT * DD;          // [T, E]

    k_zero<<<1, 32>>>();
    k_router<<<TT / 8, 256>>>(x, Wg, logits);
    k_offsets<<<1, 1>>>();
    k_scatter<<<TT / 256, 256>>>();

    dim3 gup(HH / BN, TT / BM, EE);
    k_ggemm<DD, HH, true><<<gup, 256>>>(x, W1);

    dim3 gdn(DD / BN, TT / BM, EE);
    k_ggemm<HH, DD, false><<<gdn, 256>>>(nullptr, W2);

    k_combine<<<(TT * DD / 4 + 255) / 256, 256>>>(y);
}

// round 14
// speedup vs baseline: 1.2509x; 1.2509x over previous
#include <cuda_runtime.h>
#include <math.h>
#include <stdint.h>

// Problem dims (fixed by the dataset)
#define TT 8192
#define DD 1024
#define HH 4096
#define EE 8

// GEMM tiling
#define BM 128
#define BN 128
#define BK 16
#define TM 8
#define TN 8
#define ROWF 144   // smem row stride in floats (576B); 16 8-float tiles w/ 4-float pad per 4

// ---------------- scratch (static device globals; no allocations) ----------
__device__ int   g_count[EE];
__device__ int   g_cursor[EE];
__device__ int   g_offset[EE];
__device__ int   g_sel[TT * 2];
__device__ float g_wt[TT * 2];
__device__ int   g_btok[TT * 2];
__device__ float g_bw[TT * 2];
__device__ int   g_pos[TT * 2];
__device__ float g_h[(size_t)TT * 2 * HH];
__device__ float g_yb[(size_t)TT * 2 * DD];

// ---------------- f32x2 helpers ----------------------------------------------
__device__ __forceinline__ void fma2(unsigned long long& d, unsigned long long a,
                                     unsigned long long b) {
    asm("fma.rn.f32x2 %0, %1, %2, %0;" : "+l"(d) : "l"(a), "l"(b));
}
__device__ __forceinline__ unsigned long long splat2(float a) {
    unsigned long long d;
    asm("mov.b64 %0, {%1, %1};" : "=l"(d) : "f"(a));
    return d;
}
__device__ __forceinline__ float2 unpack2(unsigned long long v) {
    float2 r;
    asm("mov.b64 {%0, %1}, %2;" : "=f"(r.x), "=f"(r.y) : "l"(v));
    return r;
}

// Fast exact-enough GELU: erf via Abramowitz-Stegun 7.1.26 (|err| <= 1.5e-7),
// branchless, MUFU-based rcp/exp. gelu(z) = 0.5*z*(1+erf(z/sqrt(2))).
__device__ __forceinline__ float fast_gelu(float z) {
    float x = fabsf(z) * 0.70710678118654752f;
    float t = __fdividef(1.f, fmaf(0.3275911f, x, 1.f));
    float p = t * fmaf(t, fmaf(t, fmaf(t, fmaf(t, 1.061405429f, -1.453152027f),
                                       1.421413741f), -0.284496736f), 0.254829592f);
    float er = fmaf(-p, __expf(-x * x), 1.f);   // erf(|x|)
    er = copysignf(er, z);
    return 0.5f * z * (1.f + er);
}

// B smem float-offset for an 8-float tile p (0..15): p*8 + (p>>2)*4.
// No overlaps; bank-verified conflict-free for LDS.128 loads and STS stores.
__device__ __forceinline__ int bskew(int p) { return p * 8 + (p >> 2) * 4; }

// ---------------- kernels ---------------------------------------------------

__global__ void k_zero() {
    if (threadIdx.x < EE) g_count[threadIdx.x] = 0;
}

__global__ void k_router(const float* __restrict__ x, const float* __restrict__ Wg,
                         float* __restrict__ out_logits) {
    int t = blockIdx.x * (blockDim.x >> 5) + (threadIdx.x >> 5);
    int lane = threadIdx.x & 31;
    if (t >= TT) return;
    const float* xr = x + (size_t)t * DD;

    float acc[EE];
#pragma unroll
    for (int e = 0; e < EE; e++) acc[e] = 0.f;
    for (int j = lane; j < DD; j += 32) {
        float xv = xr[j];
#pragma unroll
        for (int e = 0; e < EE; e++) acc[e] = fmaf(xv, Wg[e * DD + j], acc[e]);
    }
#pragma unroll
    for (int e = 0; e < EE; e++) {
#pragma unroll
        for (int o = 16; o > 0; o >>= 1) acc[e] += __shfl_xor_sync(0xffffffffu, acc[e], o);
    }
    if (lane == 0) {
        float mx = acc[0];
#pragma unroll
        for (int e = 1; e < EE; e++) mx = fmaxf(mx, acc[e]);
        float p[EE];
        float den = 0.f;
#pragma unroll
        for (int e = 0; e < EE; e++) { p[e] = expf(acc[e] - mx); den += p[e]; }
        float inv = 1.f / den;
#pragma unroll
        for (int e = 0; e < EE; e++) p[e] *= inv;

        int i0 = 0;
#pragma unroll
        for (int e = 1; e < EE; e++) if (p[e] > p[i0]) i0 = e;
        int i1 = (i0 == 0) ? 1 : 0;
#pragma unroll
        for (int e = 0; e < EE; e++) if (e != i0 && p[e] > p[i1]) i1 = e;

        float w0 = p[i0], w1 = p[i1];
        float s = 1.f / (w0 + w1);
        w0 *= s; w1 *= s;

        g_sel[t * 2] = i0; g_sel[t * 2 + 1] = i1;
        g_wt[t * 2] = w0;  g_wt[t * 2 + 1] = w1;
        atomicAdd(&g_count[i0], 1);
        atomicAdd(&g_count[i1], 1);
#pragma unroll
        for (int e = 0; e < EE; e++) out_logits[(size_t)t * EE + e] = acc[e];
    }
}

__global__ void k_offsets() {
    int o = 0;
    for (int e = 0; e < EE; e++) { g_offset[e] = o; g_cursor[e] = o; o += g_count[e]; }
}

__global__ void k_scatter() {
    int t = blockIdx.x * blockDim.x + threadIdx.x;
    if (t >= TT) return;
#pragma unroll
    for (int k = 0; k < 2; k++) {
        int e = g_sel[t * 2 + k];
        int idx = atomicAdd(&g_cursor[e], 1);
        g_btok[idx] = t;
        g_bw[idx] = g_wt[t * 2 + k];
        g_pos[t * 2 + k] = idx;
    }
}

// Grouped GEMM (fp32, packed f32x2 FMA, conflict-free smem).
// UP=true:  g_h[idx]  = gelu(x[gather] @ W1[e]) * gate
// UP=false: g_yb[idx] = g_h[idx] @ W2[e]
template<int KD, int ND, bool UP>
__global__ __launch_bounds__(256, 2)
void k_ggemm(const float* __restrict__ Ag, const float* __restrict__ Bg) {
    const int e = blockIdx.z;
    const int cnt = g_count[e];
    const int rt = blockIdx.y;
    if (rt * BM >= cnt) return;
    const int off = g_offset[e];
    const int n0 = blockIdx.x * BN;
    const int tid = threadIdx.x;

    __shared__ float As[2][BK][ROWF];
    __shared__ float Bs[2][BK][ROWF];
    __shared__ int   stok[BM];

    if (UP) {
        if (tid < BM) {
            int gr = rt * BM + tid;
            stok[tid] = g_btok[off + ((gr < cnt) ? gr : (cnt - 1))];
        }
    }
    __syncthreads();

    const float* Bexp = Bg + (size_t)e * KD * ND;

    // global-load slots
    const int ar0 = tid >> 2, ak4 = tid & 3;
    const int ar1 = ar0 + 64;
    const float* a_src0;
    const float* a_src1;
    if (UP) {
        a_src0 = Ag + (size_t)stok[ar0] * KD + ak4 * 4;
        a_src1 = Ag + (size_t)stok[ar1] * KD + ak4 * 4;
    } else {
        int g0 = rt * BM + ar0; if (g0 >= cnt) g0 = cnt - 1;
        int g1 = rt * BM + ar1; if (g1 >= cnt) g1 = cnt - 1;
        a_src0 = g_h + (size_t)(off + g0) * KD + ak4 * 4;
        a_src1 = g_h + (size_t)(off + g1) * KD + ak4 * 4;
    }
    const int bkk0 = tid >> 5, bn4 = tid & 31;
    const float* b_src0 = Bexp + (size_t)bkk0 * ND + n0 + bn4 * 4;
    const float* b_src1 = b_src0 + (size_t)8 * ND;
    // skewed store offset for this thread's float4 within a Bs row
    const int bso = bskew(bn4 >> 1) + (bn4 & 1) * 4;

    float4 pa0, pa1, pb0, pb1;

    auto fetch = [&](int kt) {
        pa0 = *(const float4*)(a_src0 + kt);
        pa1 = *(const float4*)(a_src1 + kt);
        pb0 = *(const float4*)(b_src0 + (size_t)kt * ND);
        pb1 = *(const float4*)(b_src1 + (size_t)kt * ND);
    };
    auto store = [&](int buf) {
        As[buf][ak4 * 4 + 0][ar0] = pa0.x;
        As[buf][ak4 * 4 + 1][ar0] = pa0.y;
        As[buf][ak4 * 4 + 2][ar0] = pa0.z;
        As[buf][ak4 * 4 + 3][ar0] = pa0.w;
        As[buf][ak4 * 4 + 0][ar1] = pa1.x;
        As[buf][ak4 * 4 + 1][ar1] = pa1.y;
        As[buf][ak4 * 4 + 2][ar1] = pa1.z;
        As[buf][ak4 * 4 + 3][ar1] = pa1.w;
        *(float4*)&Bs[buf][bkk0][bso]     = pb0;
        *(float4*)&Bs[buf][bkk0 + 8][bso] = pb1;
    };

    unsigned long long acc2[TM][TN / 2];
#pragma unroll
    for (int i = 0; i < TM; i++)
#pragma unroll
        for (int j = 0; j < TN / 2; j++) acc2[i][j] = 0ull;

    fetch(0);
    store(0);
    __syncthreads();

    // lane mapping: warp 4(M)x2(N); lane 4(M)x8(N)
    const int lane = tid & 31, wid = tid >> 5;
    const int wm = wid & 3, wn = wid >> 2;
    const int my = lane >> 3, nx = lane & 7;
    const int arow = wm * 32 + my * 8;          // thread's first M row in tile
    const int bofs = bskew(wn * 8 + nx);        // thread's skewed B float offset

    const int NK = KD / BK;
    for (int kt = 0; kt < NK; kt++) {
        const int cur = kt & 1;
        if (kt + 1 < NK) fetch((kt + 1) * BK);
#pragma unroll
        for (int k = 0; k < BK; k++) {
            float4 a03 = *(const float4*)&As[cur][k][arow];
            float4 a47 = *(const float4*)&As[cur][k][arow + 4];
            ulonglong2 b01 = *(const ulonglong2*)&Bs[cur][k][bofs];
            ulonglong2 b23 = *(const ulonglong2*)&Bs[cur][k][bofs + 4];
            unsigned long long bp0 = b01.x, bp1 = b01.y, bp2 = b23.x, bp3 = b23.y;
            float av[TM] = {a03.x, a03.y, a03.z, a03.w, a47.x, a47.y, a47.z, a47.w};
#pragma unroll
            for (int i = 0; i < TM; i++) {
                unsigned long long asp = splat2(av[i]);
                fma2(acc2[i][0], asp, bp0);
                fma2(acc2[i][1], asp, bp1);
                fma2(acc2[i][2], asp, bp2);
                fma2(acc2[i][3], asp, bp3);
            }
        }
        if (kt + 1 < NK) store(cur ^ 1);
        __syncthreads();
    }

    // epilogue: thread owns rows arow..arow+7, cols wn*64+nx*8..+8
    const int cc = wn * 64 + nx * 8;
#pragma unroll
    for (int i = 0; i < TM; i++) {
        int gr = rt * BM + arow + i;
        if (gr >= cnt) continue;
        float* crow;
        float gate = 1.f;
        if (UP) {
            gate = g_bw[off + gr];
            crow = g_h + (size_t)(off + gr) * ND;
        } else {
            crow = g_yb + (size_t)(off + gr) * ND;
        }
#pragma unroll
        for (int j2 = 0; j2 < TN / 2; j2 += 2) {
            float2 v0 = unpack2(acc2[i][j2]);
            float2 v1 = unpack2(acc2[i][j2 + 1]);
            float vv[4] = {v0.x, v0.y, v1.x, v1.y};
            if (UP) {
#pragma unroll
                for (int q = 0; q < 4; q++) {
                    vv[q] = fast_gelu(vv[q]) * gate;
                }
            }
            *(float4*)(crow + n0 + cc + j2 * 2) = make_float4(vv[0], vv[1], vv[2], vv[3]);
        }
    }
}

__global__ void k_combine(float* __restrict__ y) {
    int i = blockIdx.x * blockDim.x + threadIdx.x;
    const int nv = TT * DD / 4;
    if (i >= nv) return;
    int t = i / (DD / 4);
    int d4 = i % (DD / 4);
    int p0 = g_pos[2 * t], p1 = g_pos[2 * t + 1];
    float4 a = ((const float4*)(g_yb + (size_t)p0 * DD))[d4];
    float4 b = ((const float4*)(g_yb + (size_t)p1 * DD))[d4];
    float4 o = make_float4(a.x + b.x, a.y + b.y, a.z + b.z, a.w + b.w);
    ((float4*)(y + (size_t)t * DD))[d4] = o;
}

// ---------------- launch -----------------------------------------------------

extern "C" void kernel_launch(void* const* d_in, const int* in_sizes, int n_in,
                              void* d_out, int out_size) {
    const float* x  = (const float*)d_in[0];
    const float* Wg = (const float*)d_in[1];
    const float* W1 = (const float*)d_in[2];
    const float* W2 = (const float*)d_in[3];
    float* out = (float*)d_out;
    float* y = out;                                 // [T, D]
    float* logits = out + (size_t)TT * DD;          // [T, E]

    k_zero<<<1, 32>>>();
    k_router<<<TT / 8, 256>>>(x, Wg, logits);
    k_offsets<<<1, 1>>>();
    k_scatter<<<TT / 256, 256>>>();

    dim3 gup(HH / BN, TT / BM, EE);
    k_ggemm<DD, HH, true><<<gup, 256>>>(x, W1);

    dim3 gdn(DD / BN, TT / BM, EE);
    k_ggemm<HH, DD, false><<<gdn, 256>>>(nullptr, W2);

    k_combine<<<(TT * DD / 4 + 255) / 256, 256>>>(y);
}

// round 15
// speedup vs baseline: 1.2805x; 1.0237x over previous
#include <cuda_runtime.h>
#include <math.h>
#include <stdint.h>

// Problem dims (fixed by the dataset)
#define TT 8192
#define DD 1024
#define HH 4096
#define EE 8

// GEMM tiling
#define BM 128
#define BN 128
#define BK 16
#define TM 8
#define TN 8
#define ROWF 144   // smem row stride in floats (576B); 16 8-float tiles w/ 4-float pad per 4

// ---------------- scratch (static device globals; no allocations) ----------
__device__ int   g_count[EE];
__device__ int   g_cursor[EE];
__device__ int   g_offset[EE];
__device__ int   g_sel[TT * 2];
__device__ float g_wt[TT * 2];
__device__ int   g_btok[TT * 2];
__device__ float g_bw[TT * 2];
__device__ int   g_pos[TT * 2];
__device__ float g_h[(size_t)TT * 2 * HH];
__device__ float g_yb[(size_t)TT * 2 * DD];

// ---------------- f32x2 helpers ----------------------------------------------
__device__ __forceinline__ void fma2(unsigned long long& d, unsigned long long a,
                                     unsigned long long b) {
    asm("fma.rn.f32x2 %0, %1, %2, %0;" : "+l"(d) : "l"(a), "l"(b));
}
__device__ __forceinline__ unsigned long long splat2(float a) {
    unsigned long long d;
    asm("mov.b64 %0, {%1, %1};" : "=l"(d) : "f"(a));
    return d;
}
__device__ __forceinline__ float2 unpack2(unsigned long long v) {
    float2 r;
    asm("mov.b64 {%0, %1}, %2;" : "=f"(r.x), "=f"(r.y) : "l"(v));
    return r;
}

// Fast exact-enough GELU: erf via Abramowitz-Stegun 7.1.26 (|err| <= 1.5e-7).
__device__ __forceinline__ float fast_gelu(float z) {
    float x = fabsf(z) * 0.70710678118654752f;
    float t = __fdividef(1.f, fmaf(0.3275911f, x, 1.f));
    float p = t * fmaf(t, fmaf(t, fmaf(t, fmaf(t, 1.061405429f, -1.453152027f),
                                       1.421413741f), -0.284496736f), 0.254829592f);
    float er = fmaf(-p, __expf(-x * x), 1.f);   // erf(|x|)
    er = copysignf(er, z);
    return 0.5f * z * (1.f + er);
}

// B smem float-offset for an 8-float tile p (0..15): p*8 + (p>>2)*4.
// No overlaps; bank-verified conflict-free for LDS.128 loads and STS stores.
__device__ __forceinline__ int bskew(int p) { return p * 8 + (p >> 2) * 4; }

// ---------------- kernels ---------------------------------------------------

__global__ void k_zero() {
    if (threadIdx.x < EE) g_count[threadIdx.x] = 0;
}

__global__ void k_router(const float* __restrict__ x, const float* __restrict__ Wg,
                         float* __restrict__ out_logits) {
    int t = blockIdx.x * (blockDim.x >> 5) + (threadIdx.x >> 5);
    int lane = threadIdx.x & 31;
    if (t >= TT) return;
    const float* xr = x + (size_t)t * DD;

    float acc[EE];
#pragma unroll
    for (int e = 0; e < EE; e++) acc[e] = 0.f;
    for (int j = lane; j < DD; j += 32) {
        float xv = xr[j];
#pragma unroll
        for (int e = 0; e < EE; e++) acc[e] = fmaf(xv, Wg[e * DD + j], acc[e]);
    }
#pragma unroll
    for (int e = 0; e < EE; e++) {
#pragma unroll
        for (int o = 16; o > 0; o >>= 1) acc[e] += __shfl_xor_sync(0xffffffffu, acc[e], o);
    }
    if (lane == 0) {
        float mx = acc[0];
#pragma unroll
        for (int e = 1; e < EE; e++) mx = fmaxf(mx, acc[e]);
        float p[EE];
        float den = 0.f;
#pragma unroll
        for (int e = 0; e < EE; e++) { p[e] = expf(acc[e] - mx); den += p[e]; }
        float inv = 1.f / den;
#pragma unroll
        for (int e = 0; e < EE; e++) p[e] *= inv;

        int i0 = 0;
#pragma unroll
        for (int e = 1; e < EE; e++) if (p[e] > p[i0]) i0 = e;
        int i1 = (i0 == 0) ? 1 : 0;
#pragma unroll
        for (int e = 0; e < EE; e++) if (e != i0 && p[e] > p[i1]) i1 = e;

        float w0 = p[i0], w1 = p[i1];
        float s = 1.f / (w0 + w1);
        w0 *= s; w1 *= s;

        g_sel[t * 2] = i0; g_sel[t * 2 + 1] = i1;
        g_wt[t * 2] = w0;  g_wt[t * 2 + 1] = w1;
        atomicAdd(&g_count[i0], 1);
        atomicAdd(&g_count[i1], 1);
#pragma unroll
        for (int e = 0; e < EE; e++) out_logits[(size_t)t * EE + e] = acc[e];
    }
}

__global__ void k_offsets() {
    int o = 0;
    for (int e = 0; e < EE; e++) { g_offset[e] = o; g_cursor[e] = o; o += g_count[e]; }
}

__global__ void k_scatter() {
    int t = blockIdx.x * blockDim.x + threadIdx.x;
    if (t >= TT) return;
#pragma unroll
    for (int k = 0; k < 2; k++) {
        int e = g_sel[t * 2 + k];
        int idx = atomicAdd(&g_cursor[e], 1);
        g_btok[idx] = t;
        g_bw[idx] = g_wt[t * 2 + k];
        g_pos[t * 2 + k] = idx;
    }
}

// Grouped GEMM (fp32, packed f32x2 FMA, conflict-free smem, 4-stage ring,
// barrier every 2 iterations).
// UP=true:  g_h[idx]  = gelu(x[gather] @ W1[e]) * gate
// UP=false: g_yb[idx] = g_h[idx] @ W2[e]
template<int KD, int ND, bool UP>
__global__ __launch_bounds__(256, 2)
void k_ggemm(const float* __restrict__ Ag, const float* __restrict__ Bg) {
    const int e = blockIdx.z;
    const int cnt = g_count[e];
    const int rt = blockIdx.y;
    if (rt * BM >= cnt) return;
    const int off = g_offset[e];
    const int n0 = blockIdx.x * BN;
    const int tid = threadIdx.x;

    __shared__ float As[4][BK][ROWF];
    __shared__ float Bs[4][BK][ROWF];
    __shared__ int   stok[BM];

    if (UP) {
        if (tid < BM) {
            int gr = rt * BM + tid;
            stok[tid] = g_btok[off + ((gr < cnt) ? gr : (cnt - 1))];
        }
    }
    __syncthreads();

    const float* Bexp = Bg + (size_t)e * KD * ND;

    // global-load slots
    const int ar0 = tid >> 2, ak4 = tid & 3;
    const int ar1 = ar0 + 64;
    const float* a_src0;
    const float* a_src1;
    if (UP) {
        a_src0 = Ag + (size_t)stok[ar0] * KD + ak4 * 4;
        a_src1 = Ag + (size_t)stok[ar1] * KD + ak4 * 4;
    } else {
        int g0 = rt * BM + ar0; if (g0 >= cnt) g0 = cnt - 1;
        int g1 = rt * BM + ar1; if (g1 >= cnt) g1 = cnt - 1;
        a_src0 = g_h + (size_t)(off + g0) * KD + ak4 * 4;
        a_src1 = g_h + (size_t)(off + g1) * KD + ak4 * 4;
    }
    const int bkk0 = tid >> 5, bn4 = tid & 31;
    const float* b_src0 = Bexp + (size_t)bkk0 * ND + n0 + bn4 * 4;
    const float* b_src1 = b_src0 + (size_t)8 * ND;
    // skewed store offset for this thread's float4 within a Bs row
    const int bso = bskew(bn4 >> 1) + (bn4 & 1) * 4;

    float4 pa0, pa1, pb0, pb1;

    auto fetch = [&](int kt) {
        pa0 = *(const float4*)(a_src0 + kt);
        pa1 = *(const float4*)(a_src1 + kt);
        pb0 = *(const float4*)(b_src0 + (size_t)kt * ND);
        pb1 = *(const float4*)(b_src1 + (size_t)kt * ND);
    };
    auto store = [&](int buf) {
        As[buf][ak4 * 4 + 0][ar0] = pa0.x;
        As[buf][ak4 * 4 + 1][ar0] = pa0.y;
        As[buf][ak4 * 4 + 2][ar0] = pa0.z;
        As[buf][ak4 * 4 + 3][ar0] = pa0.w;
        As[buf][ak4 * 4 + 0][ar1] = pa1.x;
        As[buf][ak4 * 4 + 1][ar1] = pa1.y;
        As[buf][ak4 * 4 + 2][ar1] = pa1.z;
        As[buf][ak4 * 4 + 3][ar1] = pa1.w;
        *(float4*)&Bs[buf][bkk0][bso]     = pb0;
        *(float4*)&Bs[buf][bkk0 + 8][bso] = pb1;
    };

    unsigned long long acc2[TM][TN / 2];
#pragma unroll
    for (int i = 0; i < TM; i++)
#pragma unroll
        for (int j = 0; j < TN / 2; j++) acc2[i][j] = 0ull;

    // prologue: fill stages 0 and 1
    fetch(0);
    store(0);
    fetch(BK);
    store(1);
    __syncthreads();

    // lane mapping: warp 4(M)x2(N); lane 4(M)x8(N)
    const int lane = tid & 31, wid = tid >> 5;
    const int wm = wid & 3, wn = wid >> 2;
    const int my = lane >> 3, nx = lane & 7;
    const int arow = wm * 32 + my * 8;          // thread's first M row in tile
    const int bofs = bskew(wn * 8 + nx);        // thread's skewed B float offset

    const int NK = KD / BK;                     // divisible by 2 (64 or 256 k)
    for (int kt = 0; kt < NK; kt++) {
        const int cur = kt & 3;
        if (kt + 2 < NK) fetch((kt + 2) * BK);  // fetch two stages ahead
#pragma unroll
        for (int k = 0; k < BK; k++) {
            float4 a03 = *(const float4*)&As[cur][k][arow];
            float4 a47 = *(const float4*)&As[cur][k][arow + 4];
            ulonglong2 b01 = *(const ulonglong2*)&Bs[cur][k][bofs];
            ulonglong2 b23 = *(const ulonglong2*)&Bs[cur][k][bofs + 4];
            unsigned long long bp0 = b01.x, bp1 = b01.y, bp2 = b23.x, bp3 = b23.y;
            float av[TM] = {a03.x, a03.y, a03.z, a03.w, a47.x, a47.y, a47.z, a47.w};
#pragma unroll
            for (int i = 0; i < TM; i++) {
                unsigned long long asp = splat2(av[i]);
                fma2(acc2[i][0], asp, bp0);
                fma2(acc2[i][1], asp, bp1);
                fma2(acc2[i][2], asp, bp2);
                fma2(acc2[i][3], asp, bp3);
            }
        }
        if (kt + 2 < NK) store((kt + 2) & 3);   // store two stages ahead
        if (kt & 1) __syncthreads();            // barrier every 2 iterations
    }

    // epilogue: thread owns rows arow..arow+7, cols wn*64+nx*8..+8
    const int cc = wn * 64 + nx * 8;
#pragma unroll
    for (int i = 0; i < TM; i++) {
        int gr = rt * BM + arow + i;
        if (gr >= cnt) continue;
        float* crow;
        float gate = 1.f;
        if (UP) {
            gate = g_bw[off + gr];
            crow = g_h + (size_t)(off + gr) * ND;
        } else {
            crow = g_yb + (size_t)(off + gr) * ND;
        }
#pragma unroll
        for (int j2 = 0; j2 < TN / 2; j2 += 2) {
            float2 v0 = unpack2(acc2[i][j2]);
            float2 v1 = unpack2(acc2[i][j2 + 1]);
            float vv[4] = {v0.x, v0.y, v1.x, v1.y};
            if (UP) {
#pragma unroll
                for (int q = 0; q < 4; q++) {
                    vv[q] = fast_gelu(vv[q]) * gate;
                }
            }
            *(float4*)(crow + n0 + cc + j2 * 2) = make_float4(vv[0], vv[1], vv[2], vv[3]);
        }
    }
}

__global__ void k_combine(float* __restrict__ y) {
    int i = blockIdx.x * blockDim.x + threadIdx.x;
    const int nv = TT * DD / 4;
    if (i >= nv) return;
    int t = i / (DD / 4);
    int d4 = i % (DD / 4);
    int p0 = g_pos[2 * t], p1 = g_pos[2 * t + 1];
    float4 a = ((const float4*)(g_yb + (size_t)p0 * DD))[d4];
    float4 b = ((const float4*)(g_yb + (size_t)p1 * DD))[d4];
    float4 o = make_float4(a.x + b.x, a.y + b.y, a.z + b.z, a.w + b.w);
    ((float4*)(y + (size_t)t * DD))[d4] = o;
}

// ---------------- launch -----------------------------------------------------

extern "C" void kernel_launch(void* const* d_in, const int* in_sizes, int n_in,
                              void* d_out, int out_size) {
    const float* x  = (const float*)d_in[0];
    const float* Wg = (const float*)d_in[1];
    const float* W1 = (const float*)d_in[2];
    const float* W2 = (const float*)d_in[3];
    float* out = (float*)d_out;
    float* y = out;                                 // [T, D]
    float* logits = out + (size_t)TT * DD;          // [T, E]

    k_zero<<<1, 32>>>();
    k_router<<<TT / 8, 256>>>(x, Wg, logits);
    k_offsets<<<1, 1>>>();
    k_scatter<<<TT / 256, 256>>>();

    dim3 gup(HH / BN, TT / BM, EE);
    k_ggemm<DD, HH, true><<<gup, 256>>>(x, W1);

    dim3 gdn(DD / BN, TT / BM, EE);
    k_ggemm<HH, DD, false><<<gdn, 256>>>(nullptr, W2);

    k_combine<<<(TT * DD / 4 + 255) / 256, 256>>>(y);
}

// round 16
// speedup vs baseline: 1.2890x; 1.0067x over previous
#include <cuda_runtime.h>
#include <math.h>
#include <stdint.h>

// Problem dims (fixed by the dataset)
#define TT 8192
#define DD 1024
#define HH 4096
#define EE 8

// GEMM tiling
#define BM 128
#define BN 128
#define BK 16
#define TM 8
#define TN 8
#define ROWF 144   // smem row stride in floats (576B); 16 8-float tiles w/ 4-float pad per 4

// ---------------- scratch (static device globals; no allocations) ----------
__device__ int   g_count[EE];
__device__ int   g_cursor[EE];
__device__ int   g_offset[EE];
__device__ int   g_sel[TT * 2];
__device__ float g_wt[TT * 2];
__device__ int   g_btok[TT * 2];
__device__ float g_bw[TT * 2];
__device__ int   g_pos[TT * 2];
__device__ float g_h[(size_t)TT * 2 * HH];
__device__ float g_yb[(size_t)TT * 2 * DD];

// ---------------- helpers ------------------------------------------------------
__device__ __forceinline__ void fma2(unsigned long long& d, unsigned long long a,
                                     unsigned long long b) {
    asm("fma.rn.f32x2 %0, %1, %2, %0;" : "+l"(d) : "l"(a), "l"(b));
}
__device__ __forceinline__ unsigned long long splat2(float a) {
    unsigned long long d;
    asm("mov.b64 %0, {%1, %1};" : "=l"(d) : "f"(a));
    return d;
}
__device__ __forceinline__ float2 unpack2(unsigned long long v) {
    float2 r;
    asm("mov.b64 {%0, %1}, %2;" : "=f"(r.x), "=f"(r.y) : "l"(v));
    return r;
}
__device__ __forceinline__ uint32_t s2u(const void* p) {
    uint32_t a;
    asm("{ .reg .u64 t; cvta.to.shared.u64 t, %1; cvt.u32.u64 %0, t; }" : "=r"(a) : "l"(p));
    return a;
}
__device__ __forceinline__ void cp16(uint32_t s, const void* g) {
    asm volatile("cp.async.cg.shared.global [%0], [%1], 16;" :: "r"(s), "l"(g) : "memory");
}
__device__ __forceinline__ void cp_commit() {
    asm volatile("cp.async.commit_group;" ::: "memory");
}
__device__ __forceinline__ void cp_wait0() {
    asm volatile("cp.async.wait_group 0;" ::: "memory");
}

// Fast exact-enough GELU: erf via Abramowitz-Stegun 7.1.26 (|err| <= 1.5e-7).
__device__ __forceinline__ float fast_gelu(float z) {
    float x = fabsf(z) * 0.70710678118654752f;
    float t = __fdividef(1.f, fmaf(0.3275911f, x, 1.f));
    float p = t * fmaf(t, fmaf(t, fmaf(t, fmaf(t, 1.061405429f, -1.453152027f),
                                       1.421413741f), -0.284496736f), 0.254829592f);
    float er = fmaf(-p, __expf(-x * x), 1.f);   // erf(|x|)
    er = copysignf(er, z);
    return 0.5f * z * (1.f + er);
}

// B smem float-offset for an 8-float tile p (0..15): p*8 + (p>>2)*4.
// No overlaps; bank-verified conflict-free for LDS.128 loads and STS/cp stores.
__device__ __forceinline__ int bskew(int p) { return p * 8 + (p >> 2) * 4; }

// ---------------- kernels ---------------------------------------------------

__global__ void k_zero() {
    if (threadIdx.x < EE) g_count[threadIdx.x] = 0;
}

__global__ void k_router(const float* __restrict__ x, const float* __restrict__ Wg,
                         float* __restrict__ out_logits) {
    int t = blockIdx.x * (blockDim.x >> 5) + (threadIdx.x >> 5);
    int lane = threadIdx.x & 31;
    if (t >= TT) return;
    const float* xr = x + (size_t)t * DD;

    float acc[EE];
#pragma unroll
    for (int e = 0; e < EE; e++) acc[e] = 0.f;
    for (int j = lane; j < DD; j += 32) {
        float xv = xr[j];
#pragma unroll
        for (int e = 0; e < EE; e++) acc[e] = fmaf(xv, Wg[e * DD + j], acc[e]);
    }
#pragma unroll
    for (int e = 0; e < EE; e++) {
#pragma unroll
        for (int o = 16; o > 0; o >>= 1) acc[e] += __shfl_xor_sync(0xffffffffu, acc[e], o);
    }
    if (lane == 0) {
        float mx = acc[0];
#pragma unroll
        for (int e = 1; e < EE; e++) mx = fmaxf(mx, acc[e]);
        float p[EE];
        float den = 0.f;
#pragma unroll
        for (int e = 0; e < EE; e++) { p[e] = expf(acc[e] - mx); den += p[e]; }
        float inv = 1.f / den;
#pragma unroll
        for (int e = 0; e < EE; e++) p[e] *= inv;

        int i0 = 0;
#pragma unroll
        for (int e = 1; e < EE; e++) if (p[e] > p[i0]) i0 = e;
        int i1 = (i0 == 0) ? 1 : 0;
#pragma unroll
        for (int e = 0; e < EE; e++) if (e != i0 && p[e] > p[i1]) i1 = e;

        float w0 = p[i0], w1 = p[i1];
        float s = 1.f / (w0 + w1);
        w0 *= s; w1 *= s;

        g_sel[t * 2] = i0; g_sel[t * 2 + 1] = i1;
        g_wt[t * 2] = w0;  g_wt[t * 2 + 1] = w1;
        atomicAdd(&g_count[i0], 1);
        atomicAdd(&g_count[i1], 1);
#pragma unroll
        for (int e = 0; e < EE; e++) out_logits[(size_t)t * EE + e] = acc[e];
    }
}

__global__ void k_offsets() {
    int o = 0;
    for (int e = 0; e < EE; e++) { g_offset[e] = o; g_cursor[e] = o; o += g_count[e]; }
}

__global__ void k_scatter() {
    int t = blockIdx.x * blockDim.x + threadIdx.x;
    if (t >= TT) return;
#pragma unroll
    for (int k = 0; k < 2; k++) {
        int e = g_sel[t * 2 + k];
        int idx = atomicAdd(&g_cursor[e], 1);
        g_btok[idx] = t;
        g_bw[idx] = g_wt[t * 2 + k];
        g_pos[t * 2 + k] = idx;
    }
}

// Grouped GEMM (fp32, packed f32x2 FMA, conflict-free smem, 4-stage ring,
// barrier every 2 iterations, cp.async for B tiles).
// UP=true:  g_h[idx]  = gelu(x[gather] @ W1[e]) * gate
// UP=false: g_yb[idx] = g_h[idx] @ W2[e]
template<int KD, int ND, bool UP>
__global__ __launch_bounds__(256, 2)
void k_ggemm(const float* __restrict__ Ag, const float* __restrict__ Bg) {
    const int e = blockIdx.z;
    const int cnt = g_count[e];
    const int rt = blockIdx.y;
    if (rt * BM >= cnt) return;
    const int off = g_offset[e];
    const int n0 = blockIdx.x * BN;
    const int tid = threadIdx.x;

    __shared__ float As[4][BK][ROWF];
    __shared__ float Bs[4][BK][ROWF];
    __shared__ int   stok[BM];

    if (UP) {
        if (tid < BM) {
            int gr = rt * BM + tid;
            stok[tid] = g_btok[off + ((gr < cnt) ? gr : (cnt - 1))];
        }
    }
    __syncthreads();

    const float* Bexp = Bg + (size_t)e * KD * ND;

    // global-load slots
    const int ar0 = tid >> 2, ak4 = tid & 3;
    const int ar1 = ar0 + 64;
    const float* a_src0;
    const float* a_src1;
    if (UP) {
        a_src0 = Ag + (size_t)stok[ar0] * KD + ak4 * 4;
        a_src1 = Ag + (size_t)stok[ar1] * KD + ak4 * 4;
    } else {
        int g0 = rt * BM + ar0; if (g0 >= cnt) g0 = cnt - 1;
        int g1 = rt * BM + ar1; if (g1 >= cnt) g1 = cnt - 1;
        a_src0 = g_h + (size_t)(off + g0) * KD + ak4 * 4;
        a_src1 = g_h + (size_t)(off + g1) * KD + ak4 * 4;
    }
    const int bkk0 = tid >> 5, bn4 = tid & 31;
    const float* b_src0 = Bexp + (size_t)bkk0 * ND + n0 + bn4 * 4;
    const float* b_src1 = b_src0 + (size_t)8 * ND;
    // skewed store offset for this thread's float4 within a Bs row
    const int bso = bskew(bn4 >> 1) + (bn4 & 1) * 4;
    const uint32_t bs_dst0 = s2u(&Bs[0][bkk0][bso]);
    const uint32_t bs_dst1 = s2u(&Bs[0][bkk0 + 8][bso]);
    const uint32_t stage_bytes = (uint32_t)(BK * ROWF * sizeof(float));

    float4 pa0, pa1;

    auto fetchA = [&](int kt) {
        pa0 = *(const float4*)(a_src0 + kt);
        pa1 = *(const float4*)(a_src1 + kt);
    };
    auto storeA = [&](int buf) {
        As[buf][ak4 * 4 + 0][ar0] = pa0.x;
        As[buf][ak4 * 4 + 1][ar0] = pa0.y;
        As[buf][ak4 * 4 + 2][ar0] = pa0.z;
        As[buf][ak4 * 4 + 3][ar0] = pa0.w;
        As[buf][ak4 * 4 + 0][ar1] = pa1.x;
        As[buf][ak4 * 4 + 1][ar1] = pa1.y;
        As[buf][ak4 * 4 + 2][ar1] = pa1.z;
        As[buf][ak4 * 4 + 3][ar1] = pa1.w;
    };
    auto cpB = [&](int kt, int buf) {
        cp16(bs_dst0 + (uint32_t)buf * stage_bytes, b_src0 + (size_t)kt * ND);
        cp16(bs_dst1 + (uint32_t)buf * stage_bytes, b_src1 + (size_t)kt * ND);
        cp_commit();
    };

    unsigned long long acc2[TM][TN / 2];
#pragma unroll
    for (int i = 0; i < TM; i++)
#pragma unroll
        for (int j = 0; j < TN / 2; j++) acc2[i][j] = 0ull;

    // prologue: fill stages 0 and 1
    cpB(0, 0);
    cpB(BK, 1);
    fetchA(0);
    storeA(0);
    fetchA(BK);
    storeA(1);
    cp_wait0();
    __syncthreads();

    // lane mapping: warp 4(M)x2(N); lane 4(M)x8(N)
    const int lane = tid & 31, wid = tid >> 5;
    const int wm = wid & 3, wn = wid >> 2;
    const int my = lane >> 3, nx = lane & 7;
    const int arow = wm * 32 + my * 8;          // thread's first M row in tile
    const int bofs = bskew(wn * 8 + nx);        // thread's skewed B float offset

    const int NK = KD / BK;                     // even (64 or 256)
    for (int kt = 0; kt < NK; kt++) {
        const int cur = kt & 3;
        if (kt + 2 < NK) {
            fetchA((kt + 2) * BK);
            cpB((kt + 2) * BK, (kt + 2) & 3);   // B: direct L2 -> smem, 2 ahead
        }
#pragma unroll
        for (int k = 0; k < BK; k++) {
            float4 a03 = *(const float4*)&As[cur][k][arow];
            float4 a47 = *(const float4*)&As[cur][k][arow + 4];
            ulonglong2 b01 = *(const ulonglong2*)&Bs[cur][k][bofs];
            ulonglong2 b23 = *(const ulonglong2*)&Bs[cur][k][bofs + 4];
            unsigned long long bp0 = b01.x, bp1 = b01.y, bp2 = b23.x, bp3 = b23.y;
            float av[TM] = {a03.x, a03.y, a03.z, a03.w, a47.x, a47.y, a47.z, a47.w};
#pragma unroll
            for (int i = 0; i < TM; i++) {
                unsigned long long asp = splat2(av[i]);
                fma2(acc2[i][0], asp, bp0);
                fma2(acc2[i][1], asp, bp1);
                fma2(acc2[i][2], asp, bp2);
                fma2(acc2[i][3], asp, bp3);
            }
        }
        if (kt + 2 < NK) storeA((kt + 2) & 3);  // A: register-staged transpose, 2 ahead
        if (kt & 1) {                           // barrier every 2 iterations
            cp_wait0();
            __syncthreads();
        }
    }

    // epilogue: thread owns rows arow..arow+7, cols wn*64+nx*8..+8
    const int cc = wn * 64 + nx * 8;
#pragma unroll
    for (int i = 0; i < TM; i++) {
        int gr = rt * BM + arow + i;
        if (gr >= cnt) continue;
        float* crow;
        float gate = 1.f;
        if (UP) {
            gate = g_bw[off + gr];
            crow = g_h + (size_t)(off + gr) * ND;
        } else {
            crow = g_yb + (size_t)(off + gr) * ND;
        }
#pragma unroll
        for (int j2 = 0; j2 < TN / 2; j2 += 2) {
            float2 v0 = unpack2(acc2[i][j2]);
            float2 v1 = unpack2(acc2[i][j2 + 1]);
            float vv[4] = {v0.x, v0.y, v1.x, v1.y};
            if (UP) {
#pragma unroll
                for (int q = 0; q < 4; q++) {
                    vv[q] = fast_gelu(vv[q]) * gate;
                }
            }
            *(float4*)(crow + n0 + cc + j2 * 2) = make_float4(vv[0], vv[1], vv[2], vv[3]);
        }
    }
}

__global__ void k_combine(float* __restrict__ y) {
    int i = blockIdx.x * blockDim.x + threadIdx.x;
    const int nv = TT * DD / 4;
    if (i >= nv) return;
    int t = i / (DD / 4);
    int d4 = i % (DD / 4);
    int p0 = g_pos[2 * t], p1 = g_pos[2 * t + 1];
    float4 a = ((const float4*)(g_yb + (size_t)p0 * DD))[d4];
    float4 b = ((const float4*)(g_yb + (size_t)p1 * DD))[d4];
    float4 o = make_float4(a.x + b.x, a.y + b.y, a.z + b.z, a.w + b.w);
    ((float4*)(y + (size_t)t * DD))[d4] = o;
}

// ---------------- launch -----------------------------------------------------

extern "C" void kernel_launch(void* const* d_in, const int* in_sizes, int n_in,
                              void* d_out, int out_size) {
    const float* x  = (const float*)d_in[0];
    const float* Wg = (const float*)d_in[1];
    const float* W1 = (const float*)d_in[2];
    const float* W2 = (const float*)d_in[3];
    float* out = (float*)d_out;
    float* y = out;                                 // [T, D]
    float* logits = out + (size_t)TT * DD;          // [T, E]

    k_zero<<<1, 32>>>();
    k_router<<<TT / 8, 256>>>(x, Wg, logits);
    k_offsets<<<1, 1>>>();
    k_scatter<<<TT / 256, 256>>>();

    dim3 gup(HH / BN, TT / BM, EE);
    k_ggemm<DD, HH, true><<<gup, 256>>>(x, W1);

    dim3 gdn(DD / BN, TT / BM, EE);
    k_ggemm<HH, DD, false><<<gdn, 256>>>(nullptr, W2);

    k_combine<<<(TT * DD / 4 + 255) / 256, 256>>>(y);
}

// round 17
// speedup vs baseline: 1.3252x; 1.0281x over previous
#include <cuda_runtime.h>
#include <math.h>
#include <stdint.h>

// Problem dims (fixed by the dataset)
#define TT 8192
#define DD 1024
#define HH 4096
#define EE 8

// GEMM tiling
#define BM 128
#define BN 128
#define BK 16
#define TM 8
#define TN 8
#define ROWF 144   // smem row stride in floats (576B); 16 8-float tiles w/ 4-float pad per 4
#define NSTG 6     // ring stages; barrier every 3 iterations

// ---------------- scratch (static device globals; no allocations) ----------
__device__ int   g_count[EE];
__device__ int   g_cursor[EE];
__device__ int   g_offset[EE];
__device__ int   g_sel[TT * 2];
__device__ float g_wt[TT * 2];
__device__ int   g_btok[TT * 2];
__device__ float g_bw[TT * 2];
__device__ int   g_pos[TT * 2];
__device__ float g_h[(size_t)TT * 2 * HH];
__device__ float g_yb[(size_t)TT * 2 * DD];

// ---------------- helpers ------------------------------------------------------
__device__ __forceinline__ void fma2(unsigned long long& d, unsigned long long a,
                                     unsigned long long b) {
    asm("fma.rn.f32x2 %0, %1, %2, %0;" : "+l"(d) : "l"(a), "l"(b));
}
__device__ __forceinline__ unsigned long long splat2(float a) {
    unsigned long long d;
    asm("mov.b64 %0, {%1, %1};" : "=l"(d) : "f"(a));
    return d;
}
__device__ __forceinline__ float2 unpack2(unsigned long long v) {
    float2 r;
    asm("mov.b64 {%0, %1}, %2;" : "=f"(r.x), "=f"(r.y) : "l"(v));
    return r;
}
__device__ __forceinline__ uint32_t s2u(const void* p) {
    uint32_t a;
    asm("{ .reg .u64 t; cvta.to.shared.u64 t, %1; cvt.u32.u64 %0, t; }" : "=r"(a) : "l"(p));
    return a;
}
__device__ __forceinline__ void cp16(uint32_t s, const void* g) {
    asm volatile("cp.async.cg.shared.global [%0], [%1], 16;" :: "r"(s), "l"(g) : "memory");
}
__device__ __forceinline__ void cp_commit() {
    asm volatile("cp.async.commit_group;" ::: "memory");
}
__device__ __forceinline__ void cp_wait0() {
    asm volatile("cp.async.wait_group 0;" ::: "memory");
}

// Fast exact-enough GELU: erf via Abramowitz-Stegun 7.1.26 (|err| <= 1.5e-7).
__device__ __forceinline__ float fast_gelu(float z) {
    float x = fabsf(z) * 0.70710678118654752f;
    float t = __fdividef(1.f, fmaf(0.3275911f, x, 1.f));
    float p = t * fmaf(t, fmaf(t, fmaf(t, fmaf(t, 1.061405429f, -1.453152027f),
                                       1.421413741f), -0.284496736f), 0.254829592f);
    float er = fmaf(-p, __expf(-x * x), 1.f);   // erf(|x|)
    er = copysignf(er, z);
    return 0.5f * z * (1.f + er);
}

// B smem float-offset for an 8-float tile p (0..15): p*8 + (p>>2)*4.
// No overlaps; bank-verified conflict-free for LDS.128 loads and STS/cp stores.
__device__ __forceinline__ int bskew(int p) { return p * 8 + (p >> 2) * 4; }

// ---------------- kernels ---------------------------------------------------

__global__ void k_zero() {
    if (threadIdx.x < EE) g_count[threadIdx.x] = 0;
}

__global__ void k_router(const float* __restrict__ x, const float* __restrict__ Wg,
                         float* __restrict__ out_logits) {
    int t = blockIdx.x * (blockDim.x >> 5) + (threadIdx.x >> 5);
    int lane = threadIdx.x & 31;
    if (t >= TT) return;
    const float* xr = x + (size_t)t * DD;

    float acc[EE];
#pragma unroll
    for (int e = 0; e < EE; e++) acc[e] = 0.f;
    for (int j = lane; j < DD; j += 32) {
        float xv = xr[j];
#pragma unroll
        for (int e = 0; e < EE; e++) acc[e] = fmaf(xv, Wg[e * DD + j], acc[e]);
    }
#pragma unroll
    for (int e = 0; e < EE; e++) {
#pragma unroll
        for (int o = 16; o > 0; o >>= 1) acc[e] += __shfl_xor_sync(0xffffffffu, acc[e], o);
    }
    if (lane == 0) {
        float mx = acc[0];
#pragma unroll
        for (int e = 1; e < EE; e++) mx = fmaxf(mx, acc[e]);
        float p[EE];
        float den = 0.f;
#pragma unroll
        for (int e = 0; e < EE; e++) { p[e] = expf(acc[e] - mx); den += p[e]; }
        float inv = 1.f / den;
#pragma unroll
        for (int e = 0; e < EE; e++) p[e] *= inv;

        int i0 = 0;
#pragma unroll
        for (int e = 1; e < EE; e++) if (p[e] > p[i0]) i0 = e;
        int i1 = (i0 == 0) ? 1 : 0;
#pragma unroll
        for (int e = 0; e < EE; e++) if (e != i0 && p[e] > p[i1]) i1 = e;

        float w0 = p[i0], w1 = p[i1];
        float s = 1.f / (w0 + w1);
        w0 *= s; w1 *= s;

        g_sel[t * 2] = i0; g_sel[t * 2 + 1] = i1;
        g_wt[t * 2] = w0;  g_wt[t * 2 + 1] = w1;
        atomicAdd(&g_count[i0], 1);
        atomicAdd(&g_count[i1], 1);
#pragma unroll
        for (int e = 0; e < EE; e++) out_logits[(size_t)t * EE + e] = acc[e];
    }
}

__global__ void k_offsets() {
    int o = 0;
    for (int e = 0; e < EE; e++) { g_offset[e] = o; g_cursor[e] = o; o += g_count[e]; }
}

__global__ void k_scatter() {
    int t = blockIdx.x * blockDim.x + threadIdx.x;
    if (t >= TT) return;
#pragma unroll
    for (int k = 0; k < 2; k++) {
        int e = g_sel[t * 2 + k];
        int idx = atomicAdd(&g_cursor[e], 1);
        g_btok[idx] = t;
        g_bw[idx] = g_wt[t * 2 + k];
        g_pos[t * 2 + k] = idx;
    }
}

// Grouped GEMM (fp32, packed f32x2 FMA, conflict-free smem, 6-stage ring,
// barrier every 3 iterations, cp.async for B tiles).
// UP=true:  g_h[idx]  = gelu(x[gather] @ W1[e]) * gate
// UP=false: g_yb[idx] = g_h[idx] @ W2[e]
template<int KD, int ND, bool UP>
__global__ __launch_bounds__(256, 2)
void k_ggemm(const float* __restrict__ Ag, const float* __restrict__ Bg) {
    const int e = blockIdx.z;
    const int cnt = g_count[e];
    const int rt = blockIdx.y;
    if (rt * BM >= cnt) return;
    const int off = g_offset[e];
    const int n0 = blockIdx.x * BN;
    const int tid = threadIdx.x;

    __shared__ float As[NSTG][BK][ROWF];
    __shared__ float Bs[NSTG][BK][ROWF];
    __shared__ int   stok[BM];

    if (UP) {
        if (tid < BM) {
            int gr = rt * BM + tid;
            stok[tid] = g_btok[off + ((gr < cnt) ? gr : (cnt - 1))];
        }
    }
    __syncthreads();

    const float* Bexp = Bg + (size_t)e * KD * ND;

    // global-load slots
    const int ar0 = tid >> 2, ak4 = tid & 3;
    const int ar1 = ar0 + 64;
    const float* a_src0;
    const float* a_src1;
    if (UP) {
        a_src0 = Ag + (size_t)stok[ar0] * KD + ak4 * 4;
        a_src1 = Ag + (size_t)stok[ar1] * KD + ak4 * 4;
    } else {
        int g0 = rt * BM + ar0; if (g0 >= cnt) g0 = cnt - 1;
        int g1 = rt * BM + ar1; if (g1 >= cnt) g1 = cnt - 1;
        a_src0 = g_h + (size_t)(off + g0) * KD + ak4 * 4;
        a_src1 = g_h + (size_t)(off + g1) * KD + ak4 * 4;
    }
    const int bkk0 = tid >> 5, bn4 = tid & 31;
    const float* b_src0 = Bexp + (size_t)bkk0 * ND + n0 + bn4 * 4;
    const float* b_src1 = b_src0 + (size_t)8 * ND;
    // skewed store offset for this thread's float4 within a Bs row
    const int bso = bskew(bn4 >> 1) + (bn4 & 1) * 4;
    const uint32_t bs_dst0 = s2u(&Bs[0][bkk0][bso]);
    const uint32_t bs_dst1 = s2u(&Bs[0][bkk0 + 8][bso]);
    const uint32_t stage_bytes = (uint32_t)(BK * ROWF * sizeof(float));

    float4 pa0, pa1;

    auto fetchA = [&](int kt) {
        pa0 = *(const float4*)(a_src0 + kt);
        pa1 = *(const float4*)(a_src1 + kt);
    };
    auto storeA = [&](int buf) {
        As[buf][ak4 * 4 + 0][ar0] = pa0.x;
        As[buf][ak4 * 4 + 1][ar0] = pa0.y;
        As[buf][ak4 * 4 + 2][ar0] = pa0.z;
        As[buf][ak4 * 4 + 3][ar0] = pa0.w;
        As[buf][ak4 * 4 + 0][ar1] = pa1.x;
        As[buf][ak4 * 4 + 1][ar1] = pa1.y;
        As[buf][ak4 * 4 + 2][ar1] = pa1.z;
        As[buf][ak4 * 4 + 3][ar1] = pa1.w;
    };
    auto cpB = [&](int kt, int buf) {
        cp16(bs_dst0 + (uint32_t)buf * stage_bytes, b_src0 + (size_t)kt * ND);
        cp16(bs_dst1 + (uint32_t)buf * stage_bytes, b_src1 + (size_t)kt * ND);
        cp_commit();
    };

    unsigned long long acc2[TM][TN / 2];
#pragma unroll
    for (int i = 0; i < TM; i++)
#pragma unroll
        for (int j = 0; j < TN / 2; j++) acc2[i][j] = 0ull;

    // prologue: fill stages 0..2
    cpB(0, 0);
    cpB(BK, 1);
    cpB(2 * BK, 2);
    fetchA(0);
    storeA(0);
    fetchA(BK);
    storeA(1);
    fetchA(2 * BK);
    storeA(2);
    cp_wait0();
    __syncthreads();

    // lane mapping: warp 4(M)x2(N); lane 4(M)x8(N)
    const int lane = tid & 31, wid = tid >> 5;
    const int wm = wid & 3, wn = wid >> 2;
    const int my = lane >> 3, nx = lane & 7;
    const int arow = wm * 32 + my * 8;          // thread's first M row in tile
    const int bofs = bskew(wn * 8 + nx);        // thread's skewed B float offset

    const int NK = KD / BK;
    int cur = 0, nxt = 3, ph = 0;               // ring stage indices, phase counter
    for (int kt = 0; kt < NK; kt++) {
        if (kt + 3 < NK) {
            fetchA((kt + 3) * BK);
            cpB((kt + 3) * BK, nxt);            // B: direct L2 -> smem, 3 ahead
        }
#pragma unroll
        for (int k = 0; k < BK; k++) {
            float4 a03 = *(const float4*)&As[cur][k][arow];
            float4 a47 = *(const float4*)&As[cur][k][arow + 4];
            ulonglong2 b01 = *(const ulonglong2*)&Bs[cur][k][bofs];
            ulonglong2 b23 = *(const ulonglong2*)&Bs[cur][k][bofs + 4];
            unsigned long long bp0 = b01.x, bp1 = b01.y, bp2 = b23.x, bp3 = b23.y;
            float av[TM] = {a03.x, a03.y, a03.z, a03.w, a47.x, a47.y, a47.z, a47.w};
#pragma unroll
            for (int i = 0; i < TM; i++) {
                unsigned long long asp = splat2(av[i]);
                fma2(acc2[i][0], asp, bp0);
                fma2(acc2[i][1], asp, bp1);
                fma2(acc2[i][2], asp, bp2);
                fma2(acc2[i][3], asp, bp3);
            }
        }
        if (kt + 3 < NK) storeA(nxt);           // A: register-staged transpose, 3 ahead
        if (ph == 2) {                           // barrier every 3 iterations
            ph = 0;
            if (kt + 1 < NK) {
                cp_wait0();
                __syncthreads();
            }
        } else {
            ph++;
        }
        cur = (cur == NSTG - 1) ? 0 : cur + 1;
        nxt = (nxt == NSTG - 1) ? 0 : nxt + 1;
    }

    // epilogue: thread owns rows arow..arow+7, cols wn*64+nx*8..+8
    const int cc = wn * 64 + nx * 8;
#pragma unroll
    for (int i = 0; i < TM; i++) {
        int gr = rt * BM + arow + i;
        if (gr >= cnt) continue;
        float* crow;
        float gate = 1.f;
        if (UP) {
            gate = g_bw[off + gr];
            crow = g_h + (size_t)(off + gr) * ND;
        } else {
            crow = g_yb + (size_t)(off + gr) * ND;
        }
#pragma unroll
        for (int j2 = 0; j2 < TN / 2; j2 += 2) {
            float2 v0 = unpack2(acc2[i][j2]);
            float2 v1 = unpack2(acc2[i][j2 + 1]);
            float vv[4] = {v0.x, v0.y, v1.x, v1.y};
            if (UP) {
#pragma unroll
                for (int q = 0; q < 4; q++) {
                    vv[q] = fast_gelu(vv[q]) * gate;
                }
            }
            *(float4*)(crow + n0 + cc + j2 * 2) = make_float4(vv[0], vv[1], vv[2], vv[3]);
        }
    }
}

__global__ void k_combine(float* __restrict__ y) {
    int i = blockIdx.x * blockDim.x + threadIdx.x;
    const int nv = TT * DD / 4;
    if (i >= nv) return;
    int t = i / (DD / 4);
    int d4 = i % (DD / 4);
    int p0 = g_pos[2 * t], p1 = g_pos[2 * t + 1];
    float4 a = ((const float4*)(g_yb + (size_t)p0 * DD))[d4];
    float4 b = ((const float4*)(g_yb + (size_t)p1 * DD))[d4];
    float4 o = make_float4(a.x + b.x, a.y + b.y, a.z + b.z, a.w + b.w);
    ((float4*)(y + (size_t)t * DD))[d4] = o;
}

// ---------------- launch -----------------------------------------------------

extern "C" void kernel_launch(void* const* d_in, const int* in_sizes, int n_in,
                              void* d_out, int out_size) {
    const float* x  = (const float*)d_in[0];
    const float* Wg = (const float*)d_in[1];
    const float* W1 = (const float*)d_in[2];
    const float* W2 = (const float*)d_in[3];
    float* out = (float*)d_out;
    float* y = out;                                 // [T, D]
    float* logits = out + (size_t)TT * DD;          // [T, E]

    k_zero<<<1, 32>>>();
    k_router<<<TT / 8, 256>>>(x, Wg, logits);
    k_offsets<<<1, 1>>>();
    k_scatter<<<TT / 256, 256>>>();

    dim3 gup(HH / BN, TT / BM, EE);
    k_ggemm<DD, HH, true><<<gup, 256>>>(x, W1);

    dim3 gdn(DD / BN, TT / BM, EE);
    k_ggemm<HH, DD, false><<<gdn, 256>>>(nullptr, W2);

    k_combine<<<(TT * DD / 4 + 255) / 256, 256>>>(y);
}